// round 14
// baseline (speedup 1.0000x reference)
#include <cuda_runtime.h>
#include <cuda_fp16.h>
#include <cstdint>
#include <cstddef>

// Problem constants
#define BB 8
#define NN 2048
#define DD 1024
#define CC 1024
#define HH 4096
#define HH2 (2*HH)
#define MM (BB*NN)          // 16384
#define EPSF 1e-6f

typedef __half fp16;

// ===========================================================================
// Helpers
// ===========================================================================
__device__ __forceinline__ uint32_t smem_u32(const void* p) {
    uint32_t a;
    asm("{ .reg .u64 t; cvta.to.shared.u64 t, %1; cvt.u32.u64 %0, t; }" : "=r"(a) : "l"(p));
    return a;
}
__device__ __forceinline__ void ldsm4(uint32_t* r, uint32_t addr) {
    asm volatile("ldmatrix.sync.aligned.m8n8.x4.shared.b16 {%0,%1,%2,%3}, [%4];"
        : "=r"(r[0]), "=r"(r[1]), "=r"(r[2]), "=r"(r[3]) : "r"(addr));
}
__device__ __forceinline__ void mma16816(float* d, const uint32_t* a, const uint32_t* b) {
    asm volatile("mma.sync.aligned.m16n8k16.row.col.f32.f16.f16.f32 "
        "{%0,%1,%2,%3}, {%4,%5,%6,%7}, {%8,%9}, {%0,%1,%2,%3};"
        : "+f"(d[0]), "+f"(d[1]), "+f"(d[2]), "+f"(d[3])
        : "r"(a[0]), "r"(a[1]), "r"(a[2]), "r"(a[3]), "r"(b[0]), "r"(b[1]));
}
__device__ __forceinline__ void cp_async16(uint32_t dst, const void* src) {
    asm volatile("cp.async.cg.shared.global [%0], [%1], 16;"
        :: "r"(dst), "l"(__cvta_generic_to_global(src)));
}
#define CP_COMMIT()  asm volatile("cp.async.commit_group;" ::: "memory")
#define CP_WAIT(n)   asm volatile("cp.async.wait_group %0;" :: "n"(n) : "memory")

__device__ __forceinline__ void split_h(float x, fp16& h, fp16& l) {
    h = __float2half_rn(x);
    l = __float2half_rn(x - __half2float(h));
}
__device__ __forceinline__ uint32_t pack_h2(fp16 a, fp16 b) {
    __half2 p; p.x = a; p.y = b;
    return *(uint32_t*)&p;
}

// Shared epilogue element writer (outmode semantics identical across kernels)
__device__ __forceinline__ void epilogue_pair(
    int outmode, int row, int col, int N, float x0, float x1, float alpha,
    float* __restrict__ Cf, fp16* __restrict__ OutH, fp16* __restrict__ OutL,
    const float* __restrict__ bias, const float* __restrict__ addm,
    const int* __restrict__ positions, const float* __restrict__ invf)
{
    x0 *= alpha; x1 *= alpha;
    if (outmode == 0) {
        const size_t idx = (size_t)row * N + col;
        if (bias) { x0 += bias[col]; x1 += bias[col + 1]; }
        if (addm) {
            const float2 a2 = *(const float2*)&addm[idx];
            x0 += a2.x; x1 += a2.y;
        }
        *(float2*)&Cf[idx] = make_float2(x0, x1);
    } else if (outmode == 1) {
        const size_t idx = (size_t)row * N + col;
        if (bias) { const float bb = bias[row]; x0 += bb; x1 += bb; }
        *(uint32_t*)(OutH + idx) = pack_h2(__float2half_rn(x0), __float2half_rn(x1));
    } else if (outmode == 2) {
        const float pv = (x0 / (1.0f + __expf(-x0))) * x1;
        OutH[(size_t)row * (N >> 1) + (col >> 1)] = __float2half_rn(pv);
    } else {
        const float p = (float)__ldg(&positions[row]);
        float sn, cs;
        sincosf(p * __ldg(&invf[col >> 1]), &sn, &cs);
        const float r1 = x0 * cs - x1 * sn;
        const float r2 = x0 * sn + x1 * cs;
        const size_t idx = (size_t)row * N + col;
        if (outmode == 3) {
            fp16 h1, l1, h2, l2;
            split_h(r1, h1, l1); split_h(r2, h2, l2);
            *(uint32_t*)(OutH + idx) = pack_h2(h1, h2);
            *(uint32_t*)(OutL + idx) = pack_h2(l1, l2);
        } else {
            *(uint32_t*)(OutH + idx) = pack_h2(__float2half_rn(r1), __float2half_rn(r2));
        }
    }
}

// ===========================================================================
// Scratch (device globals)
// ===========================================================================
__device__ __align__(16) fp16 g_wqT[DD*DD];
__device__ __align__(16) fp16 g_wkT[DD*DD];
__device__ __align__(16) fp16 g_wvT[DD*DD];
__device__ __align__(16) fp16 g_wcT[DD*DD];
__device__ __align__(16) fp16 g_w13T[(size_t)HH2*DD];   // interleaved w1/w3 rows
__device__ __align__(16) fp16 g_w2T[(size_t)DD*HH];
__device__ __align__(16) fp16 g_nctx_h[CC*DD], g_nctx_l[CC*DD];
__device__ __align__(16) fp16 g_k[CC*DD];
__device__ __align__(16) fp16 g_vT[DD*CC];
__device__ __align__(16) fp16 g_nq_h[(size_t)MM*DD], g_nq_l[(size_t)MM*DD];
__device__ __align__(16) fp16 g_q_h[(size_t)MM*DD], g_q_l[(size_t)MM*DD];
__device__ __align__(16) fp16 g_z1[(size_t)MM*CC];
__device__ __align__(16) fp16 g_attn1[(size_t)MM*DD];
__device__ float g_yf[(size_t)MM*DD];
__device__ float g_ao[(size_t)MM*DD];
__device__ __align__(16) fp16 g_h1[(size_t)MM*DD];
__device__ __align__(16) fp16 g_p1[(size_t)MM*HH];
__device__ float g_invf[512];

// ===========================================================================
// Small GEMM (context path): 256 threads, CTA 128x128, BK=64, 2-stage.
// ===========================================================================
#define TILE_BYTES (128 * 72 * 2)   // 18432

template <bool SPLIT>
__device__ __forceinline__ void stage_load(
    uint32_t sm_stage, const fp16* __restrict__ Ah, const fp16* __restrict__ Al,
    const fp16* __restrict__ B, int bm, int bn, int K, int k0, int tid)
{
    constexpr int NT = SPLIT ? 3 : 2;
    #pragma unroll
    for (int t = 0; t < NT; t++) {
        const fp16* gb;
        int brow;
        if (SPLIT) { gb = (t == 0) ? Ah : (t == 1) ? Al : B; brow = (t < 2) ? bm : bn; }
        else       { gb = (t == 0) ? Ah : B;                 brow = (t < 1) ? bm : bn; }
        gb += (size_t)brow * K + k0;
        const uint32_t sb = sm_stage + t * TILE_BYTES;
        #pragma unroll
        for (int j = 0; j < 4; j++) {
            const int c = tid + j * 256;
            const int row = c >> 3, ch = c & 7;
            cp_async16(sb + row * 144 + ch * 16, gb + (size_t)row * K + ch * 8);
        }
    }
}

template <bool SPLIT>
__global__ __launch_bounds__(256, 2)
void fp16_gemm(const fp16* __restrict__ Ah, const fp16* __restrict__ Al,
               const fp16* __restrict__ B,
               float* __restrict__ Cf, fp16* __restrict__ OutH, fp16* __restrict__ OutL,
               int outmode, int M, int N, int K, float alpha,
               const float* __restrict__ bias, const float* __restrict__ addm,
               const int* __restrict__ positions, const float* __restrict__ invf)
{
    constexpr int NSPLIT = SPLIT ? 2 : 1;
    constexpr uint32_t STB = (NSPLIT + 1) * TILE_BYTES;

    extern __shared__ char smem[];
    const uint32_t sb = smem_u32(smem);
    const int tid = threadIdx.x, wid = tid >> 5, lane = tid & 31;
    const int bm = blockIdx.y * 128, bn = blockIdx.x * 128;
    const int wm = (wid >> 1) * 32, wn = (wid & 1) * 64;

    float acc[2][8][4];
    #pragma unroll
    for (int i = 0; i < 2; i++)
        #pragma unroll
        for (int j = 0; j < 8; j++)
            #pragma unroll
            for (int q = 0; q < 4; q++) acc[i][j][q] = 0.f;

    const uint32_t aoff = (uint32_t)((wm + (lane & 15)) * 144 + (lane >> 4) * 16);
    const uint32_t boff = (uint32_t)((wn + (lane & 7) + ((lane >> 4) & 1) * 8) * 144
                                     + ((lane >> 3) & 1) * 16);

    const int S = K >> 6;
    stage_load<SPLIT>(sb, Ah, Al, B, bm, bn, K, 0, tid);
    CP_COMMIT();

    for (int s = 0; s < S; s++) {
        if (s + 1 < S) {
            stage_load<SPLIT>(sb + ((s + 1) & 1) * STB, Ah, Al, B, bm, bn, K, (s + 1) << 6, tid);
            CP_COMMIT();
            CP_WAIT(1);
        } else {
            CP_WAIT(0);
        }
        __syncthreads();

        const uint32_t stg = sb + (s & 1) * STB;
        const uint32_t tB = stg + NSPLIT * TILE_BYTES;

        #pragma unroll
        for (int ks = 0; ks < 4; ks++) {
            const uint32_t ko = ks * 32;
            uint32_t a[NSPLIT][2][4];
            uint32_t b[4][4];
            #pragma unroll
            for (int sp = 0; sp < NSPLIT; sp++)
                #pragma unroll
                for (int mt = 0; mt < 2; mt++)
                    ldsm4(a[sp][mt], stg + sp * TILE_BYTES + aoff + mt * (16 * 144) + ko);
            #pragma unroll
            for (int bt = 0; bt < 4; bt++)
                ldsm4(b[bt], tB + boff + bt * (16 * 144) + ko);
            #pragma unroll
            for (int mt = 0; mt < 2; mt++)
                #pragma unroll
                for (int bt = 0; bt < 4; bt++)
                    #pragma unroll
                    for (int hf = 0; hf < 2; hf++) {
                        const int nt = bt * 2 + hf;
                        #pragma unroll
                        for (int sp = 0; sp < NSPLIT; sp++)
                            mma16816(acc[mt][nt], a[sp][mt], &b[bt][hf * 2]);
                    }
        }
        __syncthreads();
    }

    const int g = lane >> 2, qd = lane & 3;
    #pragma unroll
    for (int mt = 0; mt < 2; mt++) {
        #pragma unroll
        for (int nt = 0; nt < 8; nt++) {
            #pragma unroll
            for (int half = 0; half < 2; half++) {
                const int row = bm + wm + mt * 16 + g + half * 8;
                const int col = bn + wn + nt * 8 + qd * 2;
                epilogue_pair(outmode, row, col, N,
                              acc[mt][nt][half * 2 + 0], acc[mt][nt][half * 2 + 1], alpha,
                              Cf, OutH, OutL, bias, addm, positions, invf);
            }
        }
    }
}

// ===========================================================================
// Big GEMM (M=16384 paths): 512 threads, CTA 256x128, BK=64, 2-stage.
// 16 warps as 4x4; warp tile 64x32. Halves B-side L2 traffic vs BM=128.
// ===========================================================================
#define TILE_A_BYTES (256 * 144)   // 36864
#define TILE_B_BYTES (128 * 144)   // 18432

template <bool SPLIT>
__device__ __forceinline__ void stage_load_big(
    uint32_t sm_stage, const fp16* __restrict__ Ah, const fp16* __restrict__ Al,
    const fp16* __restrict__ B, int bm, int bn, int K, int k0, int tid)
{
    constexpr int NSPLIT = SPLIT ? 2 : 1;
    #pragma unroll
    for (int t = 0; t < NSPLIT; t++) {
        const fp16* gb = ((t == 0) ? Ah : Al) + (size_t)bm * K + k0;
        const uint32_t sa = sm_stage + t * TILE_A_BYTES;
        #pragma unroll
        for (int j = 0; j < 4; j++) {
            const int c = tid + j * 512;         // 0..2047
            const int row = c >> 3, ch = c & 7;
            cp_async16(sa + row * 144 + ch * 16, gb + (size_t)row * K + ch * 8);
        }
    }
    {
        const fp16* gb = B + (size_t)bn * K + k0;
        const uint32_t sbB = sm_stage + NSPLIT * TILE_A_BYTES;
        #pragma unroll
        for (int j = 0; j < 2; j++) {
            const int c = tid + j * 512;         // 0..1023
            const int row = c >> 3, ch = c & 7;
            cp_async16(sbB + row * 144 + ch * 16, gb + (size_t)row * K + ch * 8);
        }
    }
}

template <bool SPLIT>
__global__ __launch_bounds__(512, 1)
void fp16_gemm_big(const fp16* __restrict__ Ah, const fp16* __restrict__ Al,
                   const fp16* __restrict__ B,
                   float* __restrict__ Cf, fp16* __restrict__ OutH, fp16* __restrict__ OutL,
                   int outmode, int M, int N, int K, float alpha,
                   const float* __restrict__ bias, const float* __restrict__ addm,
                   const int* __restrict__ positions, const float* __restrict__ invf)
{
    constexpr int NSPLIT = SPLIT ? 2 : 1;
    constexpr uint32_t STB = NSPLIT * TILE_A_BYTES + TILE_B_BYTES;

    extern __shared__ char smem[];
    const uint32_t sb = smem_u32(smem);
    const int tid = threadIdx.x, wid = tid >> 5, lane = tid & 31;
    const int bm = blockIdx.y * 256, bn = blockIdx.x * 128;
    const int wm = (wid >> 2) * 64, wn = (wid & 3) * 32;

    float acc[4][4][4];
    #pragma unroll
    for (int i = 0; i < 4; i++)
        #pragma unroll
        for (int j = 0; j < 4; j++)
            #pragma unroll
            for (int q = 0; q < 4; q++) acc[i][j][q] = 0.f;

    const uint32_t aoff = (uint32_t)((wm + (lane & 15)) * 144 + (lane >> 4) * 16);
    const uint32_t boff = (uint32_t)((wn + (lane & 7) + ((lane >> 4) & 1) * 8) * 144
                                     + ((lane >> 3) & 1) * 16);

    const int S = K >> 6;
    stage_load_big<SPLIT>(sb, Ah, Al, B, bm, bn, K, 0, tid);
    CP_COMMIT();

    for (int s = 0; s < S; s++) {
        if (s + 1 < S) {
            stage_load_big<SPLIT>(sb + ((s + 1) & 1) * STB, Ah, Al, B, bm, bn, K, (s + 1) << 6, tid);
            CP_COMMIT();
            CP_WAIT(1);
        } else {
            CP_WAIT(0);
        }
        __syncthreads();

        const uint32_t stg = sb + (s & 1) * STB;
        const uint32_t tB = stg + NSPLIT * TILE_A_BYTES;

        #pragma unroll
        for (int ks = 0; ks < 4; ks++) {
            const uint32_t ko = ks * 32;
            uint32_t a[NSPLIT][4][4];
            uint32_t b[2][4];
            #pragma unroll
            for (int sp = 0; sp < NSPLIT; sp++)
                #pragma unroll
                for (int mt = 0; mt < 4; mt++)
                    ldsm4(a[sp][mt], stg + sp * TILE_A_BYTES + aoff + mt * (16 * 144) + ko);
            #pragma unroll
            for (int bt = 0; bt < 2; bt++)
                ldsm4(b[bt], tB + boff + bt * (16 * 144) + ko);
            #pragma unroll
            for (int mt = 0; mt < 4; mt++)
                #pragma unroll
                for (int bt = 0; bt < 2; bt++)
                    #pragma unroll
                    for (int hf = 0; hf < 2; hf++) {
                        const int nt = bt * 2 + hf;
                        #pragma unroll
                        for (int sp = 0; sp < NSPLIT; sp++)
                            mma16816(acc[mt][nt], a[sp][mt], &b[bt][hf * 2]);
                    }
        }
        __syncthreads();
    }

    const int g = lane >> 2, qd = lane & 3;
    #pragma unroll
    for (int mt = 0; mt < 4; mt++) {
        #pragma unroll
        for (int nt = 0; nt < 4; nt++) {
            #pragma unroll
            for (int half = 0; half < 2; half++) {
                const int row = bm + wm + mt * 16 + g + half * 8;
                const int col = bn + wn + nt * 8 + qd * 2;
                epilogue_pair(outmode, row, col, N,
                              acc[mt][nt][half * 2 + 0], acc[mt][nt][half * 2 + 1], alpha,
                              Cf, OutH, OutL, bias, addm, positions, invf);
            }
        }
    }
}

// ===========================================================================
// Transpose + convert: src fp32 [R,C] -> dst fp16, dst row = rowmul*c + rowoff
// ===========================================================================
__global__ __launch_bounds__(256)
void transconv_kernel(const float* __restrict__ src, int R, int C,
                      fp16* __restrict__ dst, int rowmul, int rowoff)
{
    __shared__ float t[32][33];
    const int c0 = blockIdx.x * 32, r0 = blockIdx.y * 32;
    const int tx = threadIdx.x & 31, ty = threadIdx.x >> 5;
    #pragma unroll
    for (int i = 0; i < 4; i++)
        t[ty + i * 8][tx] = src[(size_t)(r0 + ty + i * 8) * C + c0 + tx];
    __syncthreads();
    #pragma unroll
    for (int i = 0; i < 4; i++) {
        const float x = t[tx][ty + i * 8];
        const size_t drow = (size_t)(c0 + ty + i * 8) * rowmul + rowoff;
        dst[drow * R + r0 + tx] = __float2half_rn(x);
    }
}

// ===========================================================================
// Block reductions (256 threads)
// ===========================================================================
__device__ __forceinline__ float block_reduce_sum(float v) {
    __shared__ float red[8];
    const int lane = threadIdx.x & 31, wid = threadIdx.x >> 5;
    #pragma unroll
    for (int o = 16; o > 0; o >>= 1) v += __shfl_down_sync(0xffffffffu, v, o);
    __syncthreads();
    if (lane == 0) red[wid] = v;
    __syncthreads();
    float r = 0.f;
    if (threadIdx.x < 8) r = red[threadIdx.x];
    if (wid == 0) {
        #pragma unroll
        for (int o = 4; o > 0; o >>= 1) r += __shfl_down_sync(0xffu, r, o);
        if (lane == 0) red[0] = r;
    }
    __syncthreads();
    return red[0];
}
__device__ __forceinline__ float block_reduce_max(float v) {
    __shared__ float red[8];
    const int lane = threadIdx.x & 31, wid = threadIdx.x >> 5;
    #pragma unroll
    for (int o = 16; o > 0; o >>= 1) v = fmaxf(v, __shfl_down_sync(0xffffffffu, v, o));
    __syncthreads();
    if (lane == 0) red[wid] = v;
    __syncthreads();
    float r = -3.0e38f;
    if (threadIdx.x < 8) r = red[threadIdx.x];
    if (wid == 0) {
        #pragma unroll
        for (int o = 4; o > 0; o >>= 1) r = fmaxf(r, __shfl_down_sync(0xffu, r, o));
        if (lane == 0) red[0] = r;
    }
    __syncthreads();
    return red[0];
}

// ===========================================================================
// inv_freq table
// ===========================================================================
__global__ void init_invf_kernel(float* __restrict__ invf)
{
    const int j = threadIdx.x;                // 512 threads
    const float L2B = 13.28771237954945f;     // log2(10000)
    invf[j] = exp2f(-(float)j * (L2B / 512.0f));
}

// ===========================================================================
// RMSNorm -> split fp16. One block (256 thr) per row of 1024.
// ===========================================================================
__global__ __launch_bounds__(256)
void rmsnorm_h_kernel(const float* __restrict__ x, const float* __restrict__ g,
                      fp16* __restrict__ oh, fp16* __restrict__ ol)
{
    const size_t row = blockIdx.x;
    const int i = threadIdx.x * 4;
    const float4 v = *(const float4*)&x[row * DD + i];
    float ss = v.x*v.x + v.y*v.y + v.z*v.z + v.w*v.w;
    ss = block_reduce_sum(ss);
    const float inv = rsqrtf(ss * (1.0f / DD) + EPSF);
    const float4 gg = *(const float4*)&g[i];
    const float o0 = v.x*inv*gg.x, o1 = v.y*inv*gg.y, o2 = v.z*inv*gg.z, o3 = v.w*inv*gg.w;
    const size_t idx = row * DD + i;
    fp16 h0,l0,h1,l1,h2,l2,h3,l3;
    split_h(o0,h0,l0); split_h(o1,h1,l1); split_h(o2,h2,l2); split_h(o3,h3,l3);
    *(uint2*)(oh + idx) = make_uint2(pack_h2(h0,h1), pack_h2(h2,h3));
    *(uint2*)(ol + idx) = make_uint2(pack_h2(l0,l1), pack_h2(l2,l3));
}

// ===========================================================================
// Gumbel + softmax over C=1024; writes log_alpha_tau, z (fp32), z fp16.
// Precise logf (fast __logf corrupts the u->1 tail); fast __expf is safe.
// ===========================================================================
__global__ __launch_bounds__(256)
void gumbel_softmax_kernel(const float* __restrict__ la, const float* __restrict__ noise,
                           const float* __restrict__ tau_p, const float* __restrict__ gns_p,
                           float* __restrict__ lat_out, float* __restrict__ z_out,
                           fp16* __restrict__ zh)
{
    const size_t row = blockIdx.x;
    const float inv_tau = 1.0f / (*tau_p);
    const float gns = *gns_p;
    const size_t base = row * CC + threadIdx.x * 4;

    const float4 la4 = *(const float4*)&la[base];
    const float4 u4  = *(const float4*)&noise[base];
    float lt[4];
    const float u[4] = {u4.x, u4.y, u4.z, u4.w};
    const float l[4] = {la4.x, la4.y, la4.z, la4.w};
    #pragma unroll
    for (int t = 0; t < 4; t++) {
        const float gum = -logf(-logf(u[t] + 1e-10f) + 1e-10f);
        lt[t] = (l[t] + gns * gum) * inv_tau;
    }
    *(float4*)&lat_out[base] = make_float4(lt[0], lt[1], lt[2], lt[3]);

    float m = fmaxf(fmaxf(lt[0], lt[1]), fmaxf(lt[2], lt[3]));
    m = block_reduce_max(m);
    float e[4], s = 0.f;
    #pragma unroll
    for (int t = 0; t < 4; t++) { e[t] = __expf(lt[t] - m); s += e[t]; }
    s = block_reduce_sum(s);
    const float invs = 1.0f / s;
    float z[4];
    #pragma unroll
    for (int t = 0; t < 4; t++) z[t] = e[t] * invs;
    *(float4*)&z_out[base] = make_float4(z[0], z[1], z[2], z[3]);
    *(uint2*)(zh + base) = make_uint2(
        pack_h2(__float2half_rn(z[0]), __float2half_rn(z[1])),
        pack_h2(__float2half_rn(z[2]), __float2half_rn(z[3])));
}

// ===========================================================================
// attn_out = rs*latents + y ; h = rmsnorm(attn_out)*g_ff -> single fp16.
// ===========================================================================
__global__ __launch_bounds__(256)
void residual_rms_kernel(const float* __restrict__ latents, const float* __restrict__ y,
                         const float* __restrict__ rs_p, const float* __restrict__ gff,
                         float* __restrict__ ao_out, fp16* __restrict__ hh)
{
    const size_t row = blockIdx.x;
    const float rs = *rs_p;
    const size_t base = row * DD + threadIdx.x * 4;
    const float4 l4 = *(const float4*)&latents[base];
    const float4 y4 = *(const float4*)&y[base];
    float4 ao;
    ao.x = rs*l4.x + y4.x; ao.y = rs*l4.y + y4.y;
    ao.z = rs*l4.z + y4.z; ao.w = rs*l4.w + y4.w;
    *(float4*)&ao_out[base] = ao;
    float ss = ao.x*ao.x + ao.y*ao.y + ao.z*ao.z + ao.w*ao.w;
    ss = block_reduce_sum(ss);
    const float inv = rsqrtf(ss * (1.0f / DD) + EPSF);
    const float4 g4 = *(const float4*)&gff[threadIdx.x * 4];
    *(uint2*)(hh + base) = make_uint2(
        pack_h2(__float2half_rn(ao.x*inv*g4.x), __float2half_rn(ao.y*inv*g4.y)),
        pack_h2(__float2half_rn(ao.z*inv*g4.z), __float2half_rn(ao.w*inv*g4.w)));
}

// ===========================================================================
// Launch
// ===========================================================================
extern "C" void kernel_launch(void* const* d_in, const int* in_sizes, int n_in,
                              void* d_out, int out_size)
{
    (void)in_sizes; (void)n_in; (void)out_size;

    const float* latents  = (const float*)d_in[0];
    const float* codebook = (const float*)d_in[1];
    const float* Wq       = (const float*)d_in[2];
    const float* Wk       = (const float*)d_in[3];
    const float* Wv       = (const float*)d_in[4];
    const float* bv       = (const float*)d_in[5];
    const float* Wc       = (const float*)d_in[6];
    const float* w1       = (const float*)d_in[7];
    const float* w2       = (const float*)d_in[8];
    const float* w3       = (const float*)d_in[9];
    const float* gctx     = (const float*)d_in[10];
    const float* gq       = (const float*)d_in[11];
    const float* gff      = (const float*)d_in[12];
    const float* noise    = (const float*)d_in[13];
    const int*   positions= (const int*)d_in[14];
    const float* tau      = (const float*)d_in[15];
    const float* rs       = (const float*)d_in[16];
    const float* gns      = (const float*)d_in[17];

    const int SMEM_SPLIT      = 2 * 3 * TILE_BYTES;                    // 110592
    const int SMEM_SINGLE     = 2 * 2 * TILE_BYTES;                    // 73728
    const int SMEM_BIG_SPLIT  = 2 * (2 * TILE_A_BYTES + TILE_B_BYTES); // 184320
    const int SMEM_BIG_SINGLE = 2 * (TILE_A_BYTES + TILE_B_BYTES);     // 110592
    cudaFuncSetAttribute(fp16_gemm<true>,      cudaFuncAttributeMaxDynamicSharedMemorySize, SMEM_SPLIT);
    cudaFuncSetAttribute(fp16_gemm<false>,     cudaFuncAttributeMaxDynamicSharedMemorySize, SMEM_SINGLE);
    cudaFuncSetAttribute(fp16_gemm_big<true>,  cudaFuncAttributeMaxDynamicSharedMemorySize, SMEM_BIG_SPLIT);
    cudaFuncSetAttribute(fp16_gemm_big<false>, cudaFuncAttributeMaxDynamicSharedMemorySize, SMEM_BIG_SINGLE);

    #define SYM(v, s) do { void* _p; cudaGetSymbolAddress(&_p, s); v = (decltype(v))_p; } while (0)
    fp16 *wqT,*wkT,*wvT,*wcT,*w13T,*w2T;
    fp16 *nctx_h,*nctx_l,*k1,*vT,*nq_h,*nq_l,*q_h,*q_l,*z1,*attn1,*h1,*p1;
    float *yf,*ao,*invf;
    SYM(wqT,g_wqT); SYM(wkT,g_wkT); SYM(wvT,g_wvT); SYM(wcT,g_wcT);
    SYM(w13T,g_w13T); SYM(w2T,g_w2T);
    SYM(nctx_h,g_nctx_h); SYM(nctx_l,g_nctx_l);
    SYM(k1,g_k); SYM(vT,g_vT);
    SYM(nq_h,g_nq_h); SYM(nq_l,g_nq_l); SYM(q_h,g_q_h); SYM(q_l,g_q_l);
    SYM(z1,g_z1); SYM(attn1,g_attn1); SYM(h1,g_h1); SYM(p1,g_p1);
    SYM(yf,g_yf); SYM(ao,g_ao);
    SYM(invf,g_invf);
    #undef SYM

    float* out_cb  = (float*)d_out;
    float* out_la  = out_cb  + (size_t)MM * DD;
    float* out_lat = out_la  + (size_t)MM * CC;
    float* out_z   = out_lat + (size_t)MM * CC;

    const float inv_scale = 1.0f / 32.0f;   // 1/sqrt(1024)

    init_invf_kernel<<<1, 512>>>(invf);
    rmsnorm_h_kernel<<<CC, 256>>>(codebook, gctx, nctx_h, nctx_l);
    rmsnorm_h_kernel<<<MM, 256>>>(latents, gq, nq_h, nq_l);
    transconv_kernel<<<dim3(DD/32, DD/32), 256>>>(Wq, DD, DD, wqT, 1, 0);
    transconv_kernel<<<dim3(DD/32, DD/32), 256>>>(Wk, DD, DD, wkT, 1, 0);
    transconv_kernel<<<dim3(DD/32, DD/32), 256>>>(Wv, DD, DD, wvT, 1, 0);
    // q = rope(nq @ Wq) -> split fp16, fused (big tile)
    fp16_gemm_big<true><<<dim3(DD/128, MM/256), 512, SMEM_BIG_SPLIT>>>(
        nq_h, nq_l, wqT, nullptr, q_h, q_l, 3, MM, DD, DD, 1.f, nullptr, nullptr, positions, invf);

    transconv_kernel<<<dim3(DD/32, DD/32), 256>>>(Wc, DD, DD, wcT, 1, 0);
    transconv_kernel<<<dim3(HH/32, DD/32), 256>>>(w1, DD, HH, w13T, 2, 0);  // even rows
    transconv_kernel<<<dim3(HH/32, DD/32), 256>>>(w3, DD, HH, w13T, 2, 1);  // odd rows
    transconv_kernel<<<dim3(DD/32, HH/32), 256>>>(w2, HH, DD, w2T, 1, 0);

    // --- context path (small kernel) ---
    fp16_gemm<true><<<dim3(DD/128, CC/128), 256, SMEM_SPLIT>>>(
        nctx_h, nctx_l, wkT, nullptr, k1, nullptr, 4, CC, DD, DD, 1.f, nullptr, nullptr, positions, invf);
    fp16_gemm<false><<<dim3(CC/128, DD/128), 256, SMEM_SINGLE>>>(
        wvT, nullptr, nctx_h, nullptr, vT, nullptr, 1, DD, CC, DD, 1.f, bv, nullptr, nullptr, nullptr);

    // log_alpha = q @ k^T / 32 (big tile)
    fp16_gemm_big<true><<<dim3(CC/128, MM/256), 512, SMEM_BIG_SPLIT>>>(
        q_h, q_l, k1, out_la, nullptr, nullptr, 0, MM, CC, DD, inv_scale, nullptr, nullptr, nullptr, nullptr);

    // gumbel + softmax
    gumbel_softmax_kernel<<<MM, 256>>>(out_la, noise, tau, gns, out_lat, out_z, z1);

    // --- attn / FFN chain (single A, big tile) ---
    fp16_gemm_big<false><<<dim3(DD/128, MM/256), 512, SMEM_BIG_SINGLE>>>(
        z1, nullptr, vT, nullptr, attn1, nullptr, 1, MM, DD, CC, 1.f, nullptr, nullptr, nullptr, nullptr);
    fp16_gemm_big<false><<<dim3(DD/128, MM/256), 512, SMEM_BIG_SINGLE>>>(
        attn1, nullptr, wcT, yf, nullptr, nullptr, 0, MM, DD, DD, 1.f, nullptr, nullptr, nullptr, nullptr);
    residual_rms_kernel<<<MM, 256>>>(latents, yf, rs, gff, ao, h1);
    fp16_gemm_big<false><<<dim3(HH2/128, MM/256), 512, SMEM_BIG_SINGLE>>>(
        h1, nullptr, w13T, nullptr, p1, nullptr, 2, MM, HH2, DD, 1.f, nullptr, nullptr, nullptr, nullptr);
    fp16_gemm_big<false><<<dim3(DD/128, MM/256), 512, SMEM_BIG_SINGLE>>>(
        p1, nullptr, w2T, out_cb, nullptr, nullptr, 0, MM, DD, HH, 1.f, nullptr, ao, nullptr, nullptr);
}

// round 15
// speedup vs baseline: 1.2061x; 1.2061x over previous
#include <cuda_runtime.h>
#include <cuda_fp16.h>
#include <cstdint>
#include <cstddef>

// Problem constants
#define BB 8
#define NN 2048
#define DD 1024
#define CC 1024
#define HH 4096
#define HH2 (2*HH)
#define MM (BB*NN)          // 16384
#define EPSF 1e-6f

typedef __half fp16;

// ===========================================================================
// Helpers
// ===========================================================================
__device__ __forceinline__ uint32_t smem_u32(const void* p) {
    uint32_t a;
    asm("{ .reg .u64 t; cvta.to.shared.u64 t, %1; cvt.u32.u64 %0, t; }" : "=r"(a) : "l"(p));
    return a;
}
__device__ __forceinline__ void ldsm4(uint32_t* r, uint32_t addr) {
    asm volatile("ldmatrix.sync.aligned.m8n8.x4.shared.b16 {%0,%1,%2,%3}, [%4];"
        : "=r"(r[0]), "=r"(r[1]), "=r"(r[2]), "=r"(r[3]) : "r"(addr));
}
__device__ __forceinline__ void mma16816(float* d, const uint32_t* a, const uint32_t* b) {
    asm volatile("mma.sync.aligned.m16n8k16.row.col.f32.f16.f16.f32 "
        "{%0,%1,%2,%3}, {%4,%5,%6,%7}, {%8,%9}, {%0,%1,%2,%3};"
        : "+f"(d[0]), "+f"(d[1]), "+f"(d[2]), "+f"(d[3])
        : "r"(a[0]), "r"(a[1]), "r"(a[2]), "r"(a[3]), "r"(b[0]), "r"(b[1]));
}
__device__ __forceinline__ void cp_async16(uint32_t dst, const void* src) {
    asm volatile("cp.async.cg.shared.global [%0], [%1], 16;"
        :: "r"(dst), "l"(__cvta_generic_to_global(src)));
}
#define CP_COMMIT()  asm volatile("cp.async.commit_group;" ::: "memory")
#define CP_WAIT(n)   asm volatile("cp.async.wait_group %0;" :: "n"(n) : "memory")

__device__ __forceinline__ void split_h(float x, fp16& h, fp16& l) {
    h = __float2half_rn(x);
    l = __float2half_rn(x - __half2float(h));
}
__device__ __forceinline__ uint32_t pack_h2(fp16 a, fp16 b) {
    __half2 p; p.x = a; p.y = b;
    return *(uint32_t*)&p;
}

// ===========================================================================
// Scratch (device globals)
// ===========================================================================
__device__ __align__(16) fp16 g_wqT[DD*DD];
__device__ __align__(16) fp16 g_wkT[DD*DD];
__device__ __align__(16) fp16 g_wvT[DD*DD];
__device__ __align__(16) fp16 g_wcT[DD*DD];
__device__ __align__(16) fp16 g_w13T[(size_t)HH2*DD];   // interleaved w1/w3 rows
__device__ __align__(16) fp16 g_w2T[(size_t)DD*HH];
__device__ __align__(16) fp16 g_nctx_h[CC*DD], g_nctx_l[CC*DD];
__device__ __align__(16) fp16 g_k[CC*DD];
__device__ __align__(16) fp16 g_vT[DD*CC];
__device__ __align__(16) fp16 g_nq_h[(size_t)MM*DD], g_nq_l[(size_t)MM*DD];
__device__ __align__(16) fp16 g_q_h[(size_t)MM*DD], g_q_l[(size_t)MM*DD];
__device__ __align__(16) fp16 g_z1[(size_t)MM*CC];
__device__ __align__(16) fp16 g_attn1[(size_t)MM*DD];
__device__ float g_yf[(size_t)MM*DD];
__device__ float g_ao[(size_t)MM*DD];
__device__ __align__(16) fp16 g_h1[(size_t)MM*DD];
__device__ __align__(16) fp16 g_p1[(size_t)MM*HH];
__device__ float g_invf[512];

// ===========================================================================
// fp16 GEMM via mma.sync: C[M,N] = alpha*A@B^T (+bias)(+addm)
//   SPLIT=true : A = Ah+Al (2 MMAs, ~22-bit A); SPLIT=false: single A (1 MMA)
// outmode: 0 = fp32 C (+col-bias/+addm), 1 = fp16 out (+row-bias),
//          2 = silu-pair fp16 out, 3 = rope + split fp16, 4 = rope + single fp16
// 256 threads, CTA 128x128, BK=64, 2-stage cp.async, pitch-72 smem (144 B).
// ===========================================================================
#define TILE_BYTES (128 * 72 * 2)   // 18432

template <bool SPLIT>
__device__ __forceinline__ void stage_load(
    uint32_t sm_stage, const fp16* __restrict__ Ah, const fp16* __restrict__ Al,
    const fp16* __restrict__ B, int bm, int bn, int K, int k0, int tid)
{
    constexpr int NT = SPLIT ? 3 : 2;
    #pragma unroll
    for (int t = 0; t < NT; t++) {
        const fp16* gb;
        int brow;
        if (SPLIT) { gb = (t == 0) ? Ah : (t == 1) ? Al : B; brow = (t < 2) ? bm : bn; }
        else       { gb = (t == 0) ? Ah : B;                 brow = (t < 1) ? bm : bn; }
        gb += (size_t)brow * K + k0;
        const uint32_t sb = sm_stage + t * TILE_BYTES;
        #pragma unroll
        for (int j = 0; j < 4; j++) {
            const int c = tid + j * 256;         // 0..1023
            const int row = c >> 3, ch = c & 7;  // 64 fp16 = 8 x 16B chunks
            cp_async16(sb + row * 144 + ch * 16, gb + (size_t)row * K + ch * 8);
        }
    }
}

template <bool SPLIT>
__global__ __launch_bounds__(256, 2)
void fp16_gemm(const fp16* __restrict__ Ah, const fp16* __restrict__ Al,
               const fp16* __restrict__ B,
               float* __restrict__ Cf, fp16* __restrict__ OutH, fp16* __restrict__ OutL,
               int outmode, int M, int N, int K, float alpha,
               const float* __restrict__ bias, const float* __restrict__ addm,
               const int* __restrict__ positions, const float* __restrict__ invf)
{
    constexpr int NSPLIT = SPLIT ? 2 : 1;
    constexpr uint32_t STB = (NSPLIT + 1) * TILE_BYTES;

    extern __shared__ char smem[];
    const uint32_t sb = smem_u32(smem);
    const int tid = threadIdx.x, wid = tid >> 5, lane = tid & 31;
    const int bm = blockIdx.y * 128, bn = blockIdx.x * 128;
    const int wm = (wid >> 1) * 32, wn = (wid & 1) * 64;

    float acc[2][8][4];
    #pragma unroll
    for (int i = 0; i < 2; i++)
        #pragma unroll
        for (int j = 0; j < 8; j++)
            #pragma unroll
            for (int q = 0; q < 4; q++) acc[i][j][q] = 0.f;

    const uint32_t aoff = (uint32_t)((wm + (lane & 15)) * 144 + (lane >> 4) * 16);
    const uint32_t boff = (uint32_t)((wn + (lane & 7) + ((lane >> 4) & 1) * 8) * 144
                                     + ((lane >> 3) & 1) * 16);

    const int S = K >> 6;   // K/64 stages
    stage_load<SPLIT>(sb, Ah, Al, B, bm, bn, K, 0, tid);
    CP_COMMIT();

    for (int s = 0; s < S; s++) {
        if (s + 1 < S) {
            stage_load<SPLIT>(sb + ((s + 1) & 1) * STB, Ah, Al, B, bm, bn, K, (s + 1) << 6, tid);
            CP_COMMIT();
            CP_WAIT(1);
        } else {
            CP_WAIT(0);
        }
        __syncthreads();

        const uint32_t stg = sb + (s & 1) * STB;
        const uint32_t tB = stg + NSPLIT * TILE_BYTES;

        #pragma unroll
        for (int ks = 0; ks < 4; ks++) {
            const uint32_t ko = ks * 32;
            uint32_t a[NSPLIT][2][4];
            uint32_t b[4][4];
            #pragma unroll
            for (int sp = 0; sp < NSPLIT; sp++)
                #pragma unroll
                for (int mt = 0; mt < 2; mt++)
                    ldsm4(a[sp][mt], stg + sp * TILE_BYTES + aoff + mt * (16 * 144) + ko);
            #pragma unroll
            for (int bt = 0; bt < 4; bt++)
                ldsm4(b[bt], tB + boff + bt * (16 * 144) + ko);
            #pragma unroll
            for (int mt = 0; mt < 2; mt++)
                #pragma unroll
                for (int bt = 0; bt < 4; bt++)
                    #pragma unroll
                    for (int hf = 0; hf < 2; hf++) {
                        const int nt = bt * 2 + hf;
                        #pragma unroll
                        for (int sp = 0; sp < NSPLIT; sp++)
                            mma16816(acc[mt][nt], a[sp][mt], &b[bt][hf * 2]);
                    }
        }
        __syncthreads();
    }

    // ---- epilogue ----
    const int g = lane >> 2, qd = lane & 3;
    #pragma unroll
    for (int mt = 0; mt < 2; mt++) {
        const int r0 = bm + wm + mt * 16 + g;
        #pragma unroll
        for (int nt = 0; nt < 8; nt++) {
            const int col = bn + wn + nt * 8 + qd * 2;
            #pragma unroll
            for (int half = 0; half < 2; half++) {
                const int row = r0 + half * 8;
                float x0 = acc[mt][nt][half * 2 + 0] * alpha;
                float x1 = acc[mt][nt][half * 2 + 1] * alpha;
                if (outmode == 0) {
                    const size_t idx = (size_t)row * N + col;
                    if (bias) { x0 += bias[col]; x1 += bias[col + 1]; }
                    if (addm) {
                        const float2 a2 = *(const float2*)&addm[idx];
                        x0 += a2.x; x1 += a2.y;
                    }
                    *(float2*)&Cf[idx] = make_float2(x0, x1);
                } else if (outmode == 1) {
                    const size_t idx = (size_t)row * N + col;
                    if (bias) { const float bb = bias[row]; x0 += bb; x1 += bb; }
                    *(uint32_t*)(OutH + idx) = pack_h2(__float2half_rn(x0), __float2half_rn(x1));
                } else if (outmode == 2) {
                    // silu-pair: (x0, x1) = (w1 val, w3 val) for output col/2
                    const float pv = (x0 / (1.0f + __expf(-x0))) * x1;
                    OutH[(size_t)row * (N >> 1) + (col >> 1)] = __float2half_rn(pv);
                } else {
                    // rope: (x0, x1) = interleaved pair, j = col/2
                    const float p = (float)__ldg(&positions[row]);
                    float sn, cs;
                    sincosf(p * __ldg(&invf[col >> 1]), &sn, &cs);
                    const float r1 = x0 * cs - x1 * sn;
                    const float r2 = x0 * sn + x1 * cs;
                    const size_t idx = (size_t)row * N + col;
                    if (outmode == 3) {
                        fp16 h1, l1, h2, l2;
                        split_h(r1, h1, l1); split_h(r2, h2, l2);
                        *(uint32_t*)(OutH + idx) = pack_h2(h1, h2);
                        *(uint32_t*)(OutL + idx) = pack_h2(l1, l2);
                    } else {
                        *(uint32_t*)(OutH + idx) = pack_h2(__float2half_rn(r1), __float2half_rn(r2));
                    }
                }
            }
        }
    }
}

// ===========================================================================
// Batched transpose + convert: up to 4 srcs (fp32 [R,C]) -> dst fp16,
// dst row = rowmul*c + rowoff(z). blockIdx.z selects the (src,dst,rowoff).
// ===========================================================================
__global__ __launch_bounds__(256)
void transconv4_kernel(const float* __restrict__ s0, const float* __restrict__ s1,
                       const float* __restrict__ s2, const float* __restrict__ s3,
                       fp16* __restrict__ d0, fp16* __restrict__ d1,
                       fp16* __restrict__ d2, fp16* __restrict__ d3,
                       int R, int C, int rowmul, int off_is_z)
{
    const int zz = blockIdx.z;
    const float* src = (zz == 0) ? s0 : (zz == 1) ? s1 : (zz == 2) ? s2 : s3;
    fp16* dst        = (zz == 0) ? d0 : (zz == 1) ? d1 : (zz == 2) ? d2 : d3;
    const int rowoff = off_is_z ? zz : 0;

    __shared__ float t[32][33];
    const int c0 = blockIdx.x * 32, r0 = blockIdx.y * 32;
    const int tx = threadIdx.x & 31, ty = threadIdx.x >> 5;
    #pragma unroll
    for (int i = 0; i < 4; i++)
        t[ty + i * 8][tx] = src[(size_t)(r0 + ty + i * 8) * C + c0 + tx];
    __syncthreads();
    #pragma unroll
    for (int i = 0; i < 4; i++) {
        const float x = t[tx][ty + i * 8];
        const size_t drow = (size_t)(c0 + ty + i * 8) * rowmul + rowoff;
        dst[drow * R + r0 + tx] = __float2half_rn(x);
    }
}

// ===========================================================================
// Block reductions (256 threads)
// ===========================================================================
__device__ __forceinline__ float block_reduce_sum(float v) {
    __shared__ float red[8];
    const int lane = threadIdx.x & 31, wid = threadIdx.x >> 5;
    #pragma unroll
    for (int o = 16; o > 0; o >>= 1) v += __shfl_down_sync(0xffffffffu, v, o);
    __syncthreads();
    if (lane == 0) red[wid] = v;
    __syncthreads();
    float r = 0.f;
    if (threadIdx.x < 8) r = red[threadIdx.x];
    if (wid == 0) {
        #pragma unroll
        for (int o = 4; o > 0; o >>= 1) r += __shfl_down_sync(0xffu, r, o);
        if (lane == 0) red[0] = r;
    }
    __syncthreads();
    return red[0];
}
__device__ __forceinline__ float block_reduce_max(float v) {
    __shared__ float red[8];
    const int lane = threadIdx.x & 31, wid = threadIdx.x >> 5;
    #pragma unroll
    for (int o = 16; o > 0; o >>= 1) v = fmaxf(v, __shfl_down_sync(0xffffffffu, v, o));
    __syncthreads();
    if (lane == 0) red[wid] = v;
    __syncthreads();
    float r = -3.0e38f;
    if (threadIdx.x < 8) r = red[threadIdx.x];
    if (wid == 0) {
        #pragma unroll
        for (int o = 4; o > 0; o >>= 1) r = fmaxf(r, __shfl_down_sync(0xffu, r, o));
        if (lane == 0) red[0] = r;
    }
    __syncthreads();
    return red[0];
}

// ===========================================================================
// RMSNorm -> split fp16; block 0 optionally also fills the invf table.
// ===========================================================================
__global__ __launch_bounds__(256)
void rmsnorm_h_kernel(const float* __restrict__ x, const float* __restrict__ g,
                      fp16* __restrict__ oh, fp16* __restrict__ ol,
                      float* __restrict__ invf)
{
    const size_t row = blockIdx.x;
    if (invf && row == 0) {
        const float L2B = 13.28771237954945f;   // log2(10000)
        const int j0 = threadIdx.x;
        invf[j0]       = exp2f(-(float)j0 * (L2B / 512.0f));
        invf[j0 + 256] = exp2f(-(float)(j0 + 256) * (L2B / 512.0f));
    }
    const int i = threadIdx.x * 4;
    const float4 v = *(const float4*)&x[row * DD + i];
    float ss = v.x*v.x + v.y*v.y + v.z*v.z + v.w*v.w;
    ss = block_reduce_sum(ss);
    const float inv = rsqrtf(ss * (1.0f / DD) + EPSF);
    const float4 gg = *(const float4*)&g[i];
    const float o0 = v.x*inv*gg.x, o1 = v.y*inv*gg.y, o2 = v.z*inv*gg.z, o3 = v.w*inv*gg.w;
    const size_t idx = row * DD + i;
    fp16 h0,l0,h1,l1,h2,l2,h3,l3;
    split_h(o0,h0,l0); split_h(o1,h1,l1); split_h(o2,h2,l2); split_h(o3,h3,l3);
    *(uint2*)(oh + idx) = make_uint2(pack_h2(h0,h1), pack_h2(h2,h3));
    *(uint2*)(ol + idx) = make_uint2(pack_h2(l0,l1), pack_h2(l2,l3));
}

// ===========================================================================
// Gumbel + softmax over C=1024; writes log_alpha_tau, z (fp32), z fp16.
// Precise logf (fast __logf corrupts the u->1 tail); fast __expf is safe.
// ===========================================================================
__global__ __launch_bounds__(256)
void gumbel_softmax_kernel(const float* __restrict__ la, const float* __restrict__ noise,
                           const float* __restrict__ tau_p, const float* __restrict__ gns_p,
                           float* __restrict__ lat_out, float* __restrict__ z_out,
                           fp16* __restrict__ zh)
{
    const size_t row = blockIdx.x;
    const float inv_tau = 1.0f / (*tau_p);
    const float gns = *gns_p;
    const size_t base = row * CC + threadIdx.x * 4;

    const float4 la4 = *(const float4*)&la[base];
    const float4 u4  = *(const float4*)&noise[base];
    float lt[4];
    const float u[4] = {u4.x, u4.y, u4.z, u4.w};
    const float l[4] = {la4.x, la4.y, la4.z, la4.w};
    #pragma unroll
    for (int t = 0; t < 4; t++) {
        const float gum = -logf(-logf(u[t] + 1e-10f) + 1e-10f);
        lt[t] = (l[t] + gns * gum) * inv_tau;
    }
    *(float4*)&lat_out[base] = make_float4(lt[0], lt[1], lt[2], lt[3]);

    float m = fmaxf(fmaxf(lt[0], lt[1]), fmaxf(lt[2], lt[3]));
    m = block_reduce_max(m);
    float e[4], s = 0.f;
    #pragma unroll
    for (int t = 0; t < 4; t++) { e[t] = __expf(lt[t] - m); s += e[t]; }
    s = block_reduce_sum(s);
    const float invs = 1.0f / s;
    float z[4];
    #pragma unroll
    for (int t = 0; t < 4; t++) z[t] = e[t] * invs;
    *(float4*)&z_out[base] = make_float4(z[0], z[1], z[2], z[3]);
    *(uint2*)(zh + base) = make_uint2(
        pack_h2(__float2half_rn(z[0]), __float2half_rn(z[1])),
        pack_h2(__float2half_rn(z[2]), __float2half_rn(z[3])));
}

// ===========================================================================
// attn_out = rs*latents + y ; h = rmsnorm(attn_out)*g_ff -> single fp16.
// ===========================================================================
__global__ __launch_bounds__(256)
void residual_rms_kernel(const float* __restrict__ latents, const float* __restrict__ y,
                         const float* __restrict__ rs_p, const float* __restrict__ gff,
                         float* __restrict__ ao_out, fp16* __restrict__ hh)
{
    const size_t row = blockIdx.x;
    const float rs = *rs_p;
    const size_t base = row * DD + threadIdx.x * 4;
    const float4 l4 = *(const float4*)&latents[base];
    const float4 y4 = *(const float4*)&y[base];
    float4 ao;
    ao.x = rs*l4.x + y4.x; ao.y = rs*l4.y + y4.y;
    ao.z = rs*l4.z + y4.z; ao.w = rs*l4.w + y4.w;
    *(float4*)&ao_out[base] = ao;
    float ss = ao.x*ao.x + ao.y*ao.y + ao.z*ao.z + ao.w*ao.w;
    ss = block_reduce_sum(ss);
    const float inv = rsqrtf(ss * (1.0f / DD) + EPSF);
    const float4 g4 = *(const float4*)&gff[threadIdx.x * 4];
    *(uint2*)(hh + base) = make_uint2(
        pack_h2(__float2half_rn(ao.x*inv*g4.x), __float2half_rn(ao.y*inv*g4.y)),
        pack_h2(__float2half_rn(ao.z*inv*g4.z), __float2half_rn(ao.w*inv*g4.w)));
}

// ===========================================================================
// Launch
// ===========================================================================
extern "C" void kernel_launch(void* const* d_in, const int* in_sizes, int n_in,
                              void* d_out, int out_size)
{
    (void)in_sizes; (void)n_in; (void)out_size;

    const float* latents  = (const float*)d_in[0];
    const float* codebook = (const float*)d_in[1];
    const float* Wq       = (const float*)d_in[2];
    const float* Wk       = (const float*)d_in[3];
    const float* Wv       = (const float*)d_in[4];
    const float* bv       = (const float*)d_in[5];
    const float* Wc       = (const float*)d_in[6];
    const float* w1       = (const float*)d_in[7];
    const float* w2       = (const float*)d_in[8];
    const float* w3       = (const float*)d_in[9];
    const float* gctx     = (const float*)d_in[10];
    const float* gq       = (const float*)d_in[11];
    const float* gff      = (const float*)d_in[12];
    const float* noise    = (const float*)d_in[13];
    const int*   positions= (const int*)d_in[14];
    const float* tau      = (const float*)d_in[15];
    const float* rs       = (const float*)d_in[16];
    const float* gns      = (const float*)d_in[17];

    const int SMEM_SPLIT  = 2 * 3 * TILE_BYTES;   // 110592 (2-stage, 3 tiles)
    const int SMEM_SINGLE = 2 * 2 * TILE_BYTES;   // 73728  (2-stage, 2 tiles)
    cudaFuncSetAttribute(fp16_gemm<true>,  cudaFuncAttributeMaxDynamicSharedMemorySize, SMEM_SPLIT);
    cudaFuncSetAttribute(fp16_gemm<false>, cudaFuncAttributeMaxDynamicSharedMemorySize, SMEM_SINGLE);

    #define SYM(v, s) do { void* _p; cudaGetSymbolAddress(&_p, s); v = (decltype(v))_p; } while (0)
    fp16 *wqT,*wkT,*wvT,*wcT,*w13T,*w2T;
    fp16 *nctx_h,*nctx_l,*k1,*vT,*nq_h,*nq_l,*q_h,*q_l,*z1,*attn1,*h1,*p1;
    float *yf,*ao,*invf;
    SYM(wqT,g_wqT); SYM(wkT,g_wkT); SYM(wvT,g_wvT); SYM(wcT,g_wcT);
    SYM(w13T,g_w13T); SYM(w2T,g_w2T);
    SYM(nctx_h,g_nctx_h); SYM(nctx_l,g_nctx_l);
    SYM(k1,g_k); SYM(vT,g_vT);
    SYM(nq_h,g_nq_h); SYM(nq_l,g_nq_l); SYM(q_h,g_q_h); SYM(q_l,g_q_l);
    SYM(z1,g_z1); SYM(attn1,g_attn1); SYM(h1,g_h1); SYM(p1,g_p1);
    SYM(yf,g_yf); SYM(ao,g_ao);
    SYM(invf,g_invf);
    #undef SYM

    float* out_cb  = (float*)d_out;
    float* out_la  = out_cb  + (size_t)MM * DD;
    float* out_lat = out_la  + (size_t)MM * CC;
    float* out_z   = out_lat + (size_t)MM * CC;

    const float inv_scale = 1.0f / 32.0f;   // 1/sqrt(1024)

    // nctx rmsnorm (block 0 also fills invf table)
    rmsnorm_h_kernel<<<CC, 256>>>(codebook, gctx, nctx_h, nctx_l, invf);
    rmsnorm_h_kernel<<<MM, 256>>>(latents, gq, nq_h, nq_l, nullptr);
    // Batched weight transposes: Wq,Wk,Wv,Wc in one launch
    transconv4_kernel<<<dim3(DD/32, DD/32, 4), 256>>>(
        Wq, Wk, Wv, Wc, wqT, wkT, wvT, wcT, DD, DD, 1, 0);
    // w1/w3 interleaved into w13T in one launch (rowoff = z)
    transconv4_kernel<<<dim3(HH/32, DD/32, 2), 256>>>(
        w1, w3, nullptr, nullptr, w13T, w13T, nullptr, nullptr, DD, HH, 2, 1);
    transconv4_kernel<<<dim3(DD/32, HH/32, 1), 256>>>(
        w2, nullptr, nullptr, nullptr, w2T, nullptr, nullptr, nullptr, HH, DD, 1, 0);

    // q = rope(nq @ Wq) -> split fp16, fused
    fp16_gemm<true><<<dim3(DD/128, MM/128), 256, SMEM_SPLIT>>>(
        nq_h, nq_l, wqT, nullptr, q_h, q_l, 3, MM, DD, DD, 1.f, nullptr, nullptr, positions, invf);

    // --- context path ---
    // k = rope(nctx @ Wk) -> single fp16, fused
    fp16_gemm<true><<<dim3(DD/128, CC/128), 256, SMEM_SPLIT>>>(
        nctx_h, nctx_l, wkT, nullptr, k1, nullptr, 4, CC, DD, DD, 1.f, nullptr, nullptr, positions, invf);
    // vT[d,c] = (nctx @ Wv + bv)^T directly: A = WvT, B = nctx, row-bias bv
    fp16_gemm<false><<<dim3(CC/128, DD/128), 256, SMEM_SINGLE>>>(
        wvT, nullptr, nctx_h, nullptr, vT, nullptr, 1, DD, CC, DD, 1.f, bv, nullptr, nullptr, nullptr);

    // log_alpha = q @ k^T / 32
    fp16_gemm<true><<<dim3(CC/128, MM/128), 256, SMEM_SPLIT>>>(
        q_h, q_l, k1, out_la, nullptr, nullptr, 0, MM, CC, DD, inv_scale, nullptr, nullptr, nullptr, nullptr);

    // gumbel + softmax
    gumbel_softmax_kernel<<<MM, 256>>>(out_la, noise, tau, gns, out_lat, out_z, z1);

    // --- attn / FFN chain (single A, 2-stage) ---
    fp16_gemm<false><<<dim3(DD/128, MM/128), 256, SMEM_SINGLE>>>(
        z1, nullptr, vT, nullptr, attn1, nullptr, 1, MM, DD, CC, 1.f, nullptr, nullptr, nullptr, nullptr);
    fp16_gemm<false><<<dim3(DD/128, MM/128), 256, SMEM_SINGLE>>>(
        attn1, nullptr, wcT, yf, nullptr, nullptr, 0, MM, DD, DD, 1.f, nullptr, nullptr, nullptr, nullptr);
    residual_rms_kernel<<<MM, 256>>>(latents, yf, rs, gff, ao, h1);
    fp16_gemm<false><<<dim3(HH2/128, MM/128), 256, SMEM_SINGLE>>>(
        h1, nullptr, w13T, nullptr, p1, nullptr, 2, MM, HH2, DD, 1.f, nullptr, nullptr, nullptr, nullptr);
    fp16_gemm<false><<<dim3(DD/128, MM/128), 256, SMEM_SINGLE>>>(
        p1, nullptr, w2T, out_cb, nullptr, nullptr, 0, MM, DD, HH, 1.f, nullptr, ao, nullptr, nullptr);
}